// round 7
// baseline (speedup 1.0000x reference)
#include <cuda_runtime.h>

#define FULL 0xFFFFFFFFu

// Problem shape (fixed): N=1, L=S=512, H=8, D=M=32
constexpr int H = 8;
constexpr int ROWS = 32;              // rows per chunk
constexpr int NCHUNK = 16;            // chunks per head
constexpr int NBLOCKS = NCHUNK * H;   // 128 CTAs per kernel
constexpr int MATS = 3 * 1024 + 32;   // KK(1024) SQQ(1024) KV(1024) Ksum(32)
constexpr float K_SCALE = 0.05892556509887896f; // 1/(3*sqrt(32))

__device__ float g_part[NBLOCKS * MATS];
__device__ float g_Qn[512 * H * 32];
__device__ float g_Kn[512 * H * 32];

// ---------------------------------------------------------------------------
// K1: LayerNorm + per-(chunk,head) partial matrices.
// ---------------------------------------------------------------------------
__global__ __launch_bounds__(256) void k1_build(
        const float* __restrict__ q, const float* __restrict__ k,
        const float* __restrict__ v, const float* __restrict__ klen) {
    __shared__ __align__(16) float sQ[ROWS][36];
    __shared__ __align__(16) float sK[ROWS][36];
    __shared__ __align__(16) float sV[ROWS][36];

    int bx = blockIdx.x;
    int h = bx & 7, c = bx >> 3;
    int tid = threadIdx.x, lane = tid & 31, w = tid >> 5;

    // ---- load raw tiles: one float4 per thread per tensor ----
    int r4 = tid >> 3, c4 = (tid & 7) * 4;
    int g4 = ((c * ROWS + r4) * H + h) * 32 + c4;
    *(float4*)&sQ[r4][c4] = *(const float4*)&q[g4];
    *(float4*)&sK[r4][c4] = *(const float4*)&k[g4];
    *(float4*)&sV[r4][c4] = *(const float4*)&v[g4];
    __syncthreads();

    // ---- LayerNorm (warp w -> rows w, w+8, w+16, w+24) ----
    #pragma unroll
    for (int rr = 0; rr < 4; rr++) {
        int r = w + rr * 8;
        float x = sQ[r][lane], y = sK[r][lane];
        float sx = x, sxx = x * x, sy = y, syy = y * y;
        #pragma unroll
        for (int o = 16; o; o >>= 1) {
            sx  += __shfl_xor_sync(FULL, sx,  o);
            sxx += __shfl_xor_sync(FULL, sxx, o);
            sy  += __shfl_xor_sync(FULL, sy,  o);
            syy += __shfl_xor_sync(FULL, syy, o);
        }
        float muq = sx * (1.0f / 32.0f);
        float vq  = fmaf(-muq, muq, sxx * (1.0f / 32.0f));
        sQ[r][lane] = (x - muq) * rsqrtf(vq + 1e-5f);
        float muk = sy * (1.0f / 32.0f);
        float vk  = fmaf(-muk, muk, syy * (1.0f / 32.0f));
        sK[r][lane] = (y - muk) * rsqrtf(vk + 1e-5f) * (K_SCALE * klen[c * ROWS + r]);
    }
    __syncthreads();

    // ---- persist normalized Q/K for K2 (fire-and-forget STG.128) ----
    *(float4*)&g_Qn[g4] = *(const float4*)&sQ[r4][c4];
    *(float4*)&g_Kn[g4] = *(const float4*)&sK[r4][c4];

    // ---- partial matrices (KK: w0-1, SQQ: w2-3, KV+Ksum: w4-7) ----
    float* outp = &g_part[bx * MATS];
    if (tid < 128) {
        int t = tid & 63;
        const float (*X)[36] = (tid < 64) ? sK : sQ;
        int a0 = (t & 7) * 4, b0 = (t >> 3) * 4;
        float acc[4][4] = {};
        #pragma unroll 4
        for (int r = 0; r < ROWS; r++) {
            float4 xa = *(const float4*)&X[r][a0];
            float4 yb = *(const float4*)&X[r][b0];
            float xs[4] = {xa.x, xa.y, xa.z, xa.w};
            float ys[4] = {yb.x, yb.y, yb.z, yb.w};
            #pragma unroll
            for (int i = 0; i < 4; i++)
                #pragma unroll
                for (int j = 0; j < 4; j++)
                    acc[i][j] = fmaf(xs[i], ys[j], acc[i][j]);
        }
        int base = (tid < 64) ? 0 : 1024;
        #pragma unroll
        for (int i = 0; i < 4; i++)
            *(float4*)&outp[base + (a0 + i) * 32 + b0] =
                make_float4(acc[i][0], acc[i][1], acc[i][2], acc[i][3]);
    } else {
        // KV[d][m] = sum_r K[r][d] V[r][m], 4x2 tile per thread
        int t = tid - 128;
        int a0 = (t & 7) * 4, b0 = (t >> 3) * 2;
        float acc[4][2] = {};
        #pragma unroll 4
        for (int r = 0; r < ROWS; r++) {
            float4 xa = *(const float4*)&sK[r][a0];
            float2 yb = *(const float2*)&sV[r][b0];
            float xs[4] = {xa.x, xa.y, xa.z, xa.w};
            #pragma unroll
            for (int i = 0; i < 4; i++) {
                acc[i][0] = fmaf(xs[i], yb.x, acc[i][0]);
                acc[i][1] = fmaf(xs[i], yb.y, acc[i][1]);
            }
        }
        #pragma unroll
        for (int i = 0; i < 4; i++)
            *(float2*)&outp[2048 + (a0 + i) * 32 + b0] =
                make_float2(acc[i][0], acc[i][1]);
        if (t < 32) {
            float s = 0.0f;
            #pragma unroll
            for (int r = 0; r < ROWS; r++) s += sK[r][t];
            outp[3072 + t] = s;
        }
    }
}

// ---------------------------------------------------------------------------
// K2: each CTA reduces its head's 16 partials straight into smem, then
// runs the epilogue for its own 32 rows.
// ---------------------------------------------------------------------------
__global__ __launch_bounds__(256) void k2_consume(
        const float* __restrict__ v, float* __restrict__ out) {
    __shared__ __align__(16) float sQ[ROWS][36];
    __shared__ __align__(16) float sK[ROWS][36];
    __shared__ __align__(16) float sV[ROWS][36];
    __shared__ float sKK[32][33];
    __shared__ float sQQ[32][33];
    __shared__ float sKV[32][33];   // KV[d][m]
    __shared__ float sKs[32];

    int bx = blockIdx.x;
    int h = bx & 7, c = bx >> 3;
    int tid = threadIdx.x, lane = tid & 31, w = tid >> 5;

    // ---- tile loads: one float4 per thread per tensor ----
    int r4 = tid >> 3, c4 = (tid & 7) * 4;
    int g4 = ((c * ROWS + r4) * H + h) * 32 + c4;
    *(float4*)&sQ[r4][c4] = *(const float4*)&g_Qn[g4];
    *(float4*)&sK[r4][c4] = *(const float4*)&g_Kn[g4];
    *(float4*)&sV[r4][c4] = *(const float4*)&v[g4];

    // ---- direct 16-way reduce of this head's partials into smem ----
    for (int i = tid; i < MATS; i += 256) {
        float s = 0.0f;
        #pragma unroll
        for (int cc = 0; cc < NCHUNK; cc++)
            s += g_part[(cc * 8 + h) * MATS + i];
        if (i < 1024)      sKK[i >> 5][i & 31] = s;
        else if (i < 2048) sQQ[(i - 1024) >> 5][i & 31] = s;
        else if (i < 3072) sKV[(i - 2048) >> 5][i & 31] = s;
        else               sKs[i - 3072] = s;
    }
    __syncthreads();

    // ---- epilogue: 4 rows per warp ----
    int r0 = w * 4;
    float o1[4] = {}, wq[4] = {}, wk[4] = {};
    #pragma unroll
    for (int d = 0; d < 32; d++) {
        float a = sKV[d][lane];     // strided, conflict-free
        float b = sKK[d][lane];
        float cc2 = sQQ[d][lane];
        #pragma unroll
        for (int r = 0; r < 4; r++) {
            float qd = sQ[r0 + r][d];   // broadcast LDS
            float kd = sK[r0 + r][d];   // broadcast LDS
            o1[r] = fmaf(qd, a,   o1[r]);
            wq[r] = fmaf(qd, b,   wq[r]);
            wk[r] = fmaf(kd, cc2, wk[r]);
        }
    }
    #pragma unroll
    for (int r = 0; r < 4; r++) {
        int rr = r0 + r;
        float qm = sQ[rr][lane], km = sK[rr][lane], vm = sV[rr][lane];
        float tn = fmaf(0.5f * wq[r], qm, qm * sKs[lane]); // norm partial
        float tc = wk[r] * km;                             // k^T SQQ k partial
        #pragma unroll
        for (int o = 16; o; o >>= 1) {
            tn += __shfl_xor_sync(FULL, tn, o);
            tc += __shfl_xor_sync(FULL, tc, o);
        }
        int l = c * ROWS + rr;
        out[(l * H + h) * 32 + lane] = (o1[r] + 0.5f * tc * vm) / tn;
    }
}

extern "C" void kernel_launch(void* const* d_in, const int* in_sizes, int n_in,
                              void* d_out, int out_size) {
    const float* q    = (const float*)d_in[0];
    const float* k    = (const float*)d_in[1];
    const float* v    = (const float*)d_in[2];
    // d_in[3] attn_mask, d_in[4] query_lengths: unused by the reference
    const float* klen = (const float*)d_in[5];
    float* out = (float*)d_out;

    k1_build<<<NBLOCKS, 256>>>(q, k, v, klen);
    k2_consume<<<NBLOCKS, 256>>>(v, out);
}